// round 8
// baseline (speedup 1.0000x reference)
#include <cuda_runtime.h>
#include <cuda_bf16.h>
#include <math.h>

#define B_  256
#define T_  256
#define E_  64
#define N_  512
#define V_  128
#define G4  2048   // 4*N
#define NBLK 128

#define KS_BF 520   // Whs stride in bf16: [col][k], padded
#define KS_W  260
#define HA_BF 72    // hA stride in bf16: [row][k] per 64-k chunk, padded
#define HA_W  36
#define Z_STRIDE 68 // z-exchange float stride

// SMEM byte offsets (recurrence)
#define OFF_WHI 0
#define OFF_WLO (64 * KS_BF * 2)                 // 66560
#define OFF_HA  (2 * 64 * KS_BF * 2)             // 133120
#define HA_BYTES (64 * HA_BF * 2)                // 9216
#define SMEM_TOTAL_LSTM (OFF_HA + 4 * HA_BYTES)  // 169984

// GEMM kernels (input/out): 4 planes of [128][36 words]
#define GW 36
#define PLANE (128 * GW)
#define SMEM_GEMM (4 * PLANE * 4)                 // 73728 bytes

// ---- scratch (static device memory; no allocations) ----
__device__ float g_xz[(size_t)T_ * B_ * G4];   // [T,B,4N] input projections (+bias)
__device__ float g_hs[(size_t)T_ * B_ * N_];   // [T,B,N] hidden states for final dense
__device__ unsigned g_hhi[2][B_ * N_ / 2];     // ping-pong h, bf16 hi plane (packed pairs)
__device__ unsigned g_hlo[2][B_ * N_ / 2];     // ping-pong h, bf16 lo plane
__device__ unsigned g_flags[NBLK * 32];        // grid barrier flags, 128B-padded

// ---------------------------------------------------------------------------
__device__ __forceinline__ float sigf(float x) { return 1.f / (1.f + __expf(-x)); }

__device__ __forceinline__ void mma_bf16(float* d, const unsigned* a, const unsigned* b) {
    asm volatile(
        "mma.sync.aligned.m16n8k16.row.col.f32.bf16.bf16.f32 "
        "{%0,%1,%2,%3}, {%4,%5,%6,%7}, {%8,%9}, {%0,%1,%2,%3};"
        : "+f"(d[0]), "+f"(d[1]), "+f"(d[2]), "+f"(d[3])
        : "r"(a[0]), "r"(a[1]), "r"(a[2]), "r"(a[3]), "r"(b[0]), "r"(b[1]));
}

__device__ __forceinline__ void ldsm_x4(unsigned* r, unsigned addr) {
    asm volatile("ldmatrix.sync.aligned.m8n8.x4.shared.b16 {%0,%1,%2,%3}, [%4];"
        : "=r"(r[0]), "=r"(r[1]), "=r"(r[2]), "=r"(r[3]) : "r"(addr));
}

__device__ __forceinline__ unsigned smem_u32(const void* p) {
    return (unsigned)__cvta_generic_to_shared(p);
}

__device__ __forceinline__ void bf16_split(float x, __nv_bfloat16& hi, __nv_bfloat16& lo) {
    hi = __float2bfloat16(x);
    lo = __float2bfloat16(x - __bfloat162float(hi));
}

__device__ __forceinline__ unsigned pack_bf2(__nv_bfloat16 lo, __nv_bfloat16 hi) {
    unsigned short ul = __bfloat16_as_ushort(lo);
    unsigned short uh = __bfloat16_as_ushort(hi);
    return (unsigned)ul | ((unsigned)uh << 16);
}

__device__ __forceinline__ void split4(float4 v, uint2& hw, uint2& lw) {
    __nv_bfloat16 h0, l0, h1, l1, h2, l2, h3, l3;
    bf16_split(v.x, h0, l0); bf16_split(v.y, h1, l1);
    bf16_split(v.z, h2, l2); bf16_split(v.w, h3, l3);
    hw = make_uint2(pack_bf2(h0, h1), pack_bf2(h2, h3));
    lw = make_uint2(pack_bf2(l0, l1), pack_bf2(l2, l3));
}

extern __shared__ char smem_raw[];

// ---------------------------------------------------------------------------
// init: split h_0 into bf16 hi/lo planes, reset barrier flags
// ---------------------------------------------------------------------------
__global__ void init_kernel(const float* __restrict__ h0) {
    int i = blockIdx.x * blockDim.x + threadIdx.x;
    if (i < B_ * N_ / 2) {
        float2 v = *(const float2*)(h0 + 2 * i);
        __nv_bfloat16 ha, la, hb, lb;
        bf16_split(v.x, ha, la); bf16_split(v.y, hb, lb);
        g_hhi[0][i] = pack_bf2(ha, hb);
        g_hlo[0][i] = pack_bf2(la, lb);
    }
    if (i < NBLK) g_flags[i * 32] = 0u;
}

// ---------------------------------------------------------------------------
// bf16x2 tensor-core GEMM core for input/out GEMMs
// ---------------------------------------------------------------------------
__device__ __forceinline__ void gemm_chunk(const unsigned* AhiW, const unsigned* AloW,
                                           const unsigned* BhiW, const unsigned* BloW,
                                           int wr, int wc, int g4r, int lk,
                                           float acc[2][8][4]) {
#pragma unroll
    for (int k16 = 0; k16 < 4; k16++) {
        unsigned aHi[2][4], aLo[2][4];
#pragma unroll
        for (int f = 0; f < 2; f++) {
            int aw = (wr + f * 16 + g4r) * GW + lk + k16 * 8;
            aHi[f][0] = AhiW[aw];          aHi[f][1] = AhiW[aw + 8 * GW];
            aHi[f][2] = AhiW[aw + 4];      aHi[f][3] = AhiW[aw + 8 * GW + 4];
            aLo[f][0] = AloW[aw];          aLo[f][1] = AloW[aw + 8 * GW];
            aLo[f][2] = AloW[aw + 4];      aLo[f][3] = AloW[aw + 8 * GW + 4];
        }
#pragma unroll
        for (int sub = 0; sub < 8; sub++) {
            int col = wc + sub * 8 + g4r;
            int bw  = col * GW + lk + k16 * 8;
            unsigned bHi[2], bLo[2];
            bHi[0] = BhiW[bw]; bHi[1] = BhiW[bw + 4];
            bLo[0] = BloW[bw]; bLo[1] = BloW[bw + 4];
#pragma unroll
            for (int f = 0; f < 2; f++) {
                mma_bf16(acc[f][sub], aHi[f], bHi);
                mma_bf16(acc[f][sub], aHi[f], bLo);
                mma_bf16(acc[f][sub], aLo[f], bHi);
            }
        }
    }
}

// ---------------------------------------------------------------------------
// Kernel A (tensor): xz[r][g] = bias[g] + sum_e emb[X[b][t]][e] * Wx[e][g]
// ---------------------------------------------------------------------------
__global__ void __launch_bounds__(256)
input_gemm_tc(const int*   __restrict__ X,
              const float* __restrict__ emb,
              const float* __restrict__ Wx,
              const float* __restrict__ bias) {
    unsigned* AhiW = (unsigned*)smem_raw;
    unsigned* AloW = AhiW + PLANE;
    unsigned* BhiW = AloW + PLANE;
    unsigned* BloW = BhiW + PLANE;
    __shared__ int xid[128];

    const int tid  = threadIdx.x;
    const int r0   = blockIdx.y * 128;
    const int g0   = blockIdx.x * 128;
    const int lane = tid & 31;
    const int wid  = tid >> 5;
    const int wr   = (wid & 3) * 32;
    const int wc   = (wid >> 2) * 64;
    const int g4r  = lane >> 2;
    const int lk   = lane & 3;
    const int lx2  = lk * 2;

    if (tid < 128) {
        int r = r0 + tid;
        xid[tid] = X[(r & 255) * T_ + (r >> 8)];
    }
    __syncthreads();

    {
        int row = tid >> 1;
        const float* src = emb + (size_t)xid[row] * E_;
        int qb = (tid & 1) * 8;
#pragma unroll
        for (int q = 0; q < 8; q++) {
            float4 v = *(const float4*)(src + (qb + q) * 4);
            uint2 hw, lw;
            split4(v, hw, lw);
            int widx = row * GW + (qb + q) * 2;
            *(uint2*)(AhiW + widx) = hw;
            *(uint2*)(AloW + widx) = lw;
        }
    }
    {
        int c = tid & 127, khalf = tid >> 7;
#pragma unroll
        for (int kk = 0; kk < 16; kk++) {
            int k0 = khalf * 32 + kk * 2;
            float a = Wx[(size_t)k0 * G4 + g0 + c];
            float b = Wx[(size_t)(k0 + 1) * G4 + g0 + c];
            __nv_bfloat16 ha, la, hb, lb;
            bf16_split(a, ha, la); bf16_split(b, hb, lb);
            int widx = c * GW + khalf * 16 + kk;
            BhiW[widx] = pack_bf2(ha, hb);
            BloW[widx] = pack_bf2(la, lb);
        }
    }
    __syncthreads();

    float acc[2][8][4];
#pragma unroll
    for (int f = 0; f < 2; f++)
#pragma unroll
        for (int s = 0; s < 8; s++)
#pragma unroll
            for (int i = 0; i < 4; i++) acc[f][s][i] = 0.f;

    gemm_chunk(AhiW, AloW, BhiW, BloW, wr, wc, g4r, lk, acc);

#pragma unroll
    for (int f = 0; f < 2; f++) {
        int rlo = r0 + wr + f * 16 + g4r;
#pragma unroll
        for (int sub = 0; sub < 8; sub++) {
            int g = g0 + wc + sub * 8 + lx2;
            float2 bb = *(const float2*)(bias + g);
            *(float2*)(g_xz + (size_t)rlo * G4 + g) =
                make_float2(acc[f][sub][0] + bb.x, acc[f][sub][1] + bb.y);
            *(float2*)(g_xz + (size_t)(rlo + 8) * G4 + g) =
                make_float2(acc[f][sub][2] + bb.x, acc[f][sub][3] + bb.y);
        }
    }
}

// ---------------------------------------------------------------------------
// Persistent LSTM recurrence:
//  - h ping-pong stored as bf16 hi/lo planes (split once at producer)
//  - staging is a raw uint4 copy (no conversion)
//  - fragment loads via ldmatrix.x4
//  - full-grid barrier (proven safe in R6)
// ---------------------------------------------------------------------------
__global__ void __launch_bounds__(256, 1)
lstm_persistent(const float* __restrict__ Wh, const float* __restrict__ c0) {
    __nv_bfloat16* WhHi = (__nv_bfloat16*)(smem_raw + OFF_WHI);
    __nv_bfloat16* WhLo = (__nv_bfloat16*)(smem_raw + OFF_WLO);
    char* hBase = smem_raw + OFF_HA;   // buf0: hi,lo ; buf1: hi,lo

    const int tid  = threadIdx.x;
    const int bid  = blockIdx.x;
    const int cg   = bid & 31;          // n-group
    const int rg   = bid >> 5;          // row-group
    const int n0   = cg * 16;
    const int r0   = rg * 64;
    const int lane = tid & 31;
    const int wid  = tid >> 5;
    const int wr   = (wid & 3) * 16;    // warp row offset
    const int wc   = (wid >> 2) * 32;   // warp col offset
    const int g4r  = lane >> 2;
    const int lk   = lane & 3;
    const int lx2  = lk * 2;

    // ---- load + split Wh slice once: WhHi/WhLo[col][k], col = g*16+j ----
    for (int idx = tid; idx < 512 * 16; idx += 256) {
        int k = idx >> 4, q = idx & 15;
        int g = q >> 2, jj = (q & 3) * 4;
        float4 w = *(const float4*)(Wh + (size_t)k * G4 + g * N_ + n0 + jj);
        int cb = g * 16 + jj;
        __nv_bfloat16 hi, lo;
        bf16_split(w.x, hi, lo); WhHi[(cb + 0) * KS_BF + k] = hi; WhLo[(cb + 0) * KS_BF + k] = lo;
        bf16_split(w.y, hi, lo); WhHi[(cb + 1) * KS_BF + k] = hi; WhLo[(cb + 1) * KS_BF + k] = lo;
        bf16_split(w.z, hi, lo); WhHi[(cb + 2) * KS_BF + k] = hi; WhLo[(cb + 2) * KS_BF + k] = lo;
        bf16_split(w.w, hi, lo); WhHi[(cb + 3) * KS_BF + k] = hi; WhLo[(cb + 3) * KS_BF + k] = lo;
    }

    // ---- cell state in registers ----
    const int prow = tid >> 2;
    const int pj0  = (tid & 3) * 4;
    float4 creg = *(const float4*)(c0 + (size_t)(r0 + prow) * N_ + n0 + pj0);

    __syncthreads();

    // ---- ldmatrix lane address components ----
    const int aRowByte = (wr + (lane & 15)) * (HA_BF * 2) + ((lane >> 4) << 4);
    const unsigned hA0hi = smem_u32(hBase) + (unsigned)aRowByte;
    const unsigned hA1hi = hA0hi + 2 * HA_BYTES;
    const int bColByte = (wc + ((lane >> 4) & 1) * 8 + (lane & 7)) * (KS_BF * 2)
                       + ((lane >> 3) & 1) * 16;
    const unsigned bHiBase = smem_u32(WhHi) + (unsigned)bColByte;
    const unsigned bLoBase = smem_u32(WhLo) + (unsigned)bColByte;

    // staging mapping: 256 threads = 2 planes x 64 rows x 2 halves
    const int splane = tid >> 7;           // 0 = hi, 1 = lo
    const int srow   = (tid >> 1) & 63;
    const int shalf  = tid & 1;            // words [shalf*16, +16)
    const int sgoff  = (r0 + srow) * (N_ / 2) + shalf * 16;
    const int ssoff  = srow * HA_W + shalf * 16;

    for (int t = 0; t < T_; t++) {
        const unsigned* __restrict__ gin = splane ? g_hlo[t & 1] : g_hhi[t & 1];
        unsigned* __restrict__ ghhi_out = g_hhi[(t + 1) & 1];
        unsigned* __restrict__ ghlo_out = g_hlo[(t + 1) & 1];

        // ---- acc init from xz ----
        float acc[4][4];
        {
            const int rlo = r0 + wr + g4r;
#pragma unroll
            for (int sub = 0; sub < 4; sub++) {
                int c    = wc + sub * 8 + lx2;
                int gate = c >> 4, jj = c & 15;
                size_t base = (size_t)t * B_ * G4 + (size_t)gate * N_ + n0 + jj;
                float2 xlo = __ldcg((const float2*)(g_xz + base + (size_t)rlo * G4));
                float2 xhi = __ldcg((const float2*)(g_xz + base + (size_t)(rlo + 8) * G4));
                acc[sub][0] = xlo.x; acc[sub][1] = xlo.y;
                acc[sub][2] = xhi.x; acc[sub][3] = xhi.y;
            }
        }

        // ---- GEMM over K=512 in 8 chunks of 64, double-buffered copy-staging ----
        uint4 pf[4];
#pragma unroll
        for (int q = 0; q < 4; q++)
            pf[q] = __ldcg((const uint4*)(gin + sgoff + q * 4));

        for (int kc = 0; kc < 8; kc++) {
            unsigned* dst = (unsigned*)(hBase + (kc & 1) * 2 * HA_BYTES + splane * HA_BYTES);
#pragma unroll
            for (int q = 0; q < 4; q++)
                *(uint4*)(dst + ssoff + q * 4) = pf[q];
            if (kc < 7) {
#pragma unroll
                for (int q = 0; q < 4; q++)
                    pf[q] = __ldcg((const uint4*)(gin + sgoff + (kc + 1) * 32 + q * 4));
            }
            __syncthreads();

            const unsigned aHiAddr = ((kc & 1) ? hA1hi : hA0hi);
            const unsigned aLoAddr = aHiAddr + HA_BYTES;
            const unsigned bKOff   = (unsigned)(kc * 128);
#pragma unroll
            for (int k16 = 0; k16 < 4; k16++) {
                unsigned aHi[4], aLo[4];
                ldsm_x4(aHi, aHiAddr + k16 * 32);
                ldsm_x4(aLo, aLoAddr + k16 * 32);
#pragma unroll
                for (int p = 0; p < 2; p++) {
                    unsigned bH[4], bL[4];
                    unsigned boff = bKOff + k16 * 32 + (unsigned)(p * 16 * KS_BF * 2);
                    ldsm_x4(bH, bHiBase + boff);
                    ldsm_x4(bL, bLoBase + boff);
                    mma_bf16(acc[2 * p],     aHi, bH);
                    mma_bf16(acc[2 * p],     aHi, bL);
                    mma_bf16(acc[2 * p],     aLo, bH);
                    mma_bf16(acc[2 * p + 1], aHi, bH + 2);
                    mma_bf16(acc[2 * p + 1], aHi, bL + 2);
                    mma_bf16(acc[2 * p + 1], aLo, bH + 2);
                }
            }
            __syncthreads();
        }

        // ---- exchange z through SMEM ----
        float* zs = (float*)hBase;
        {
            const int rl = wr + g4r;
#pragma unroll
            for (int sub = 0; sub < 4; sub++) {
                int c = wc + sub * 8 + lx2;
                *(float2*)(zs + (size_t)rl * Z_STRIDE + c)       = make_float2(acc[sub][0], acc[sub][1]);
                *(float2*)(zs + (size_t)(rl + 8) * Z_STRIDE + c) = make_float2(acc[sub][2], acc[sub][3]);
            }
        }
        __syncthreads();

        // ---- pointwise gates + c/h update; split h at producer ----
        {
            const float* zr = zs + (size_t)prow * Z_STRIDE + pj0;
            float4 zi = *(const float4*)(zr + 0);
            float4 zf = *(const float4*)(zr + 16);
            float4 zg = *(const float4*)(zr + 32);
            float4 zo = *(const float4*)(zr + 48);

            float4 hv;
            creg.x = sigf(zf.x) * creg.x + sigf(zi.x) * tanhf(zg.x); hv.x = sigf(zo.x) * tanhf(creg.x);
            creg.y = sigf(zf.y) * creg.y + sigf(zi.y) * tanhf(zg.y); hv.y = sigf(zo.y) * tanhf(creg.y);
            creg.z = sigf(zf.z) * creg.z + sigf(zi.z) * tanhf(zg.z); hv.z = sigf(zo.z) * tanhf(creg.z);
            creg.w = sigf(zf.w) * creg.w + sigf(zi.w) * tanhf(zg.w); hv.w = sigf(zo.w) * tanhf(creg.w);

            size_t off = (size_t)(r0 + prow) * N_ + n0 + pj0;
            *(float4*)(g_hs + (size_t)t * B_ * N_ + off) = hv;

            uint2 hw, lw;
            split4(hv, hw, lw);
            size_t woff = off >> 1;
            *(uint2*)(ghhi_out + woff) = hw;
            *(uint2*)(ghlo_out + woff) = lw;
        }

        // ---- full-grid barrier (all 128 blocks resident) ----
        __threadfence();
        __syncthreads();
        if (tid == 0) {
            asm volatile("st.global.release.gpu.u32 [%0], %1;"
                         :: "l"(&g_flags[bid * 32]), "r"((unsigned)(t + 1)) : "memory");
        }
        if (tid < NBLK) {
            unsigned v;
            do {
                asm volatile("ld.global.acquire.gpu.u32 %0, [%1];"
                             : "=r"(v) : "l"(&g_flags[tid * 32]) : "memory");
                if (v >= (unsigned)(t + 1)) break;
                __nanosleep(20);
            } while (true);
        }
        __syncthreads();
    }
}

// ---------------------------------------------------------------------------
// Kernel D (tensor): logits[b][t][v] = bd[v] + sum_n hs[t][b][n] * Wd[n][v]
// ---------------------------------------------------------------------------
__global__ void __launch_bounds__(256)
out_gemm_tc(const float* __restrict__ Wd,
            const float* __restrict__ bd,
            float*       __restrict__ out) {
    unsigned* AhiW = (unsigned*)smem_raw;
    unsigned* AloW = AhiW + PLANE;
    unsigned* BhiW = AloW + PLANE;
    unsigned* BloW = BhiW + PLANE;

    const int tid  = threadIdx.x;
    const int r0   = blockIdx.x * 128;
    const int lane = tid & 31;
    const int wid  = tid >> 5;
    const int wr   = (wid & 3) * 32;
    const int wc   = (wid >> 2) * 64;
    const int g4r  = lane >> 2;
    const int lk   = lane & 3;
    const int lx2  = lk * 2;

    float acc[2][8][4];
#pragma unroll
    for (int f = 0; f < 2; f++)
#pragma unroll
        for (int s = 0; s < 8; s++)
#pragma unroll
            for (int i = 0; i < 4; i++) acc[f][s][i] = 0.f;

    const int srow = tid >> 1;
    const int sqb  = (tid & 1) * 8;
    const int bc   = tid & 127;
    const int bkh  = tid >> 7;

    for (int kc = 0; kc < 8; kc++) {
#pragma unroll
        for (int q = 0; q < 8; q++) {
            float4 v = __ldcg((const float4*)(g_hs + (size_t)(r0 + srow) * N_ + kc * 64 + (sqb + q) * 4));
            uint2 hw, lw;
            split4(v, hw, lw);
            int widx = srow * GW + (sqb + q) * 2;
            *(uint2*)(AhiW + widx) = hw;
            *(uint2*)(AloW + widx) = lw;
        }
#pragma unroll
        for (int kk = 0; kk < 16; kk++) {
            int k0 = kc * 64 + bkh * 32 + kk * 2;
            float a = Wd[(size_t)k0 * V_ + bc];
            float b = Wd[(size_t)(k0 + 1) * V_ + bc];
            __nv_bfloat16 ha, la, hb, lb;
            bf16_split(a, ha, la); bf16_split(b, hb, lb);
            int widx = bc * GW + bkh * 16 + kk;
            BhiW[widx] = pack_bf2(ha, hb);
            BloW[widx] = pack_bf2(la, lb);
        }
        __syncthreads();

        gemm_chunk(AhiW, AloW, BhiW, BloW, wr, wc, g4r, lk, acc);
        __syncthreads();
    }

#pragma unroll
    for (int f = 0; f < 2; f++) {
        int rlo = r0 + wr + f * 16 + g4r;
        int t0 = rlo >> 8,        b0 = rlo & 255;
        int t1 = (rlo + 8) >> 8,  b1 = (rlo + 8) & 255;
        size_t o0 = ((size_t)b0 * T_ + t0) * V_;
        size_t o1 = ((size_t)b1 * T_ + t1) * V_;
#pragma unroll
        for (int sub = 0; sub < 8; sub++) {
            int v = wc + sub * 8 + lx2;
            float2 bb = *(const float2*)(bd + v);
            *(float2*)(out + o0 + v) = make_float2(acc[f][sub][0] + bb.x, acc[f][sub][1] + bb.y);
            *(float2*)(out + o1 + v) = make_float2(acc[f][sub][2] + bb.x, acc[f][sub][3] + bb.y);
        }
    }
}

// ---------------------------------------------------------------------------
extern "C" void kernel_launch(void* const* d_in, const int* in_sizes, int n_in,
                              void* d_out, int out_size) {
    const int*   X    = (const int*)  d_in[0];
    const float* h0   = (const float*)d_in[1];
    const float* c0   = (const float*)d_in[2];
    const float* emb  = (const float*)d_in[3];
    const float* Wx   = (const float*)d_in[4];
    const float* Wh   = (const float*)d_in[5];
    const float* bias = (const float*)d_in[6];
    const float* Wd   = (const float*)d_in[7];
    const float* bd   = (const float*)d_in[8];
    float* out = (float*)d_out;

    cudaFuncSetAttribute(lstm_persistent, cudaFuncAttributeMaxDynamicSharedMemorySize, SMEM_TOTAL_LSTM);
    cudaFuncSetAttribute(input_gemm_tc,  cudaFuncAttributeMaxDynamicSharedMemorySize, SMEM_GEMM);
    cudaFuncSetAttribute(out_gemm_tc,    cudaFuncAttributeMaxDynamicSharedMemorySize, SMEM_GEMM);

    init_kernel<<<(B_ * N_ / 2 + 255) / 256, 256>>>(h0);
    input_gemm_tc<<<dim3(G4 / 128, (T_ * B_) / 128), 256, SMEM_GEMM>>>(X, emb, Wx, bias);
    lstm_persistent<<<NBLK, 256, SMEM_TOTAL_LSTM>>>(Wh, c0);
    out_gemm_tc<<<(T_ * B_) / 128, 256, SMEM_GEMM>>>(Wd, bd, out);
}

// round 9
// speedup vs baseline: 1.1914x; 1.1914x over previous
#include <cuda_runtime.h>
#include <cuda_bf16.h>
#include <math.h>

#define B_  256
#define T_  256
#define E_  64
#define N_  512
#define V_  128
#define G4  2048   // 4*N
#define NBLK 128

#define KS_BF 520   // Whs stride in bf16: [col][k], padded
#define KS_W  260
#define HA_BF 72    // hA stride in bf16: [row][k] per 64-k chunk, padded
#define HA_W  36
#define Z_STRIDE 68 // z-exchange float stride

// SMEM byte offsets (recurrence)
#define OFF_WHI 0
#define OFF_WLO (64 * KS_BF * 2)                 // 66560
#define OFF_HA  (2 * 64 * KS_BF * 2)             // 133120
#define HA_BYTES (64 * HA_BF * 2)                // 9216
#define SMEM_TOTAL_LSTM (OFF_HA + 4 * HA_BYTES)  // 169984

// GEMM kernels (input/out): 4 planes of [128][36 words]
#define GW 36
#define PLANE (128 * GW)
#define SMEM_GEMM (4 * PLANE * 4)                 // 73728 bytes

// ---- scratch (static device memory; no allocations) ----
__device__ float g_xz[(size_t)T_ * B_ * G4];   // [T,B,4N] input projections (+bias)
__device__ float g_hs[(size_t)T_ * B_ * N_];   // [T,B,N] hidden states for final dense
__device__ float g_h[2][B_ * N_];              // ping-pong h
__device__ unsigned g_flags[NBLK * 32];        // grid barrier flags, 128B-padded

// ---------------------------------------------------------------------------
__device__ __forceinline__ float sigf(float x) {
    return __fdividef(1.f, 1.f + __expf(-x));
}

// overflow-safe fast tanh: |err| ~ 1e-6 rel, no inf/nan for any x
__device__ __forceinline__ float tanhf_fast(float x) {
    float t = __expf(-2.f * fabsf(x));
    float r = __fdividef(1.f - t, 1.f + t);
    return copysignf(r, x);
}

__device__ __forceinline__ void mma_bf16(float* d, const unsigned* a, const unsigned* b) {
    asm volatile(
        "mma.sync.aligned.m16n8k16.row.col.f32.bf16.bf16.f32 "
        "{%0,%1,%2,%3}, {%4,%5,%6,%7}, {%8,%9}, {%0,%1,%2,%3};"
        : "+f"(d[0]), "+f"(d[1]), "+f"(d[2]), "+f"(d[3])
        : "r"(a[0]), "r"(a[1]), "r"(a[2]), "r"(a[3]), "r"(b[0]), "r"(b[1]));
}

__device__ __forceinline__ void bf16_split(float x, __nv_bfloat16& hi, __nv_bfloat16& lo) {
    hi = __float2bfloat16(x);
    lo = __float2bfloat16(x - __bfloat162float(hi));
}

__device__ __forceinline__ unsigned pack_bf2(__nv_bfloat16 lo, __nv_bfloat16 hi) {
    unsigned short ul = __bfloat16_as_ushort(lo);
    unsigned short uh = __bfloat16_as_ushort(hi);
    return (unsigned)ul | ((unsigned)uh << 16);
}

__device__ __forceinline__ void split4(float4 v, uint2& hw, uint2& lw) {
    __nv_bfloat16 h0, l0, h1, l1, h2, l2, h3, l3;
    bf16_split(v.x, h0, l0); bf16_split(v.y, h1, l1);
    bf16_split(v.z, h2, l2); bf16_split(v.w, h3, l3);
    hw = make_uint2(pack_bf2(h0, h1), pack_bf2(h2, h3));
    lw = make_uint2(pack_bf2(l0, l1), pack_bf2(l2, l3));
}

extern __shared__ char smem_raw[];

// ---------------------------------------------------------------------------
// init: load h_0, reset barrier flags (part of the graph -> replay-safe)
// ---------------------------------------------------------------------------
__global__ void init_kernel(const float* __restrict__ h0) {
    int i = blockIdx.x * blockDim.x + threadIdx.x;
    if (i < B_ * N_) g_h[0][i] = h0[i];
    if (i < NBLK)    g_flags[i * 32] = 0u;
}

// ---------------------------------------------------------------------------
// bf16x2 tensor-core GEMM core for input/out GEMMs
// ---------------------------------------------------------------------------
__device__ __forceinline__ void gemm_chunk(const unsigned* AhiW, const unsigned* AloW,
                                           const unsigned* BhiW, const unsigned* BloW,
                                           int wr, int wc, int g4r, int lk,
                                           float acc[2][8][4]) {
#pragma unroll
    for (int k16 = 0; k16 < 4; k16++) {
        unsigned aHi[2][4], aLo[2][4];
#pragma unroll
        for (int f = 0; f < 2; f++) {
            int aw = (wr + f * 16 + g4r) * GW + lk + k16 * 8;
            aHi[f][0] = AhiW[aw];          aHi[f][1] = AhiW[aw + 8 * GW];
            aHi[f][2] = AhiW[aw + 4];      aHi[f][3] = AhiW[aw + 8 * GW + 4];
            aLo[f][0] = AloW[aw];          aLo[f][1] = AloW[aw + 8 * GW];
            aLo[f][2] = AloW[aw + 4];      aLo[f][3] = AloW[aw + 8 * GW + 4];
        }
#pragma unroll
        for (int sub = 0; sub < 8; sub++) {
            int col = wc + sub * 8 + g4r;
            int bw  = col * GW + lk + k16 * 8;
            unsigned bHi[2], bLo[2];
            bHi[0] = BhiW[bw]; bHi[1] = BhiW[bw + 4];
            bLo[0] = BloW[bw]; bLo[1] = BloW[bw + 4];
#pragma unroll
            for (int f = 0; f < 2; f++) {
                mma_bf16(acc[f][sub], aHi[f], bHi);
                mma_bf16(acc[f][sub], aHi[f], bLo);
                mma_bf16(acc[f][sub], aLo[f], bHi);
            }
        }
    }
}

// ---------------------------------------------------------------------------
// Kernel A (tensor): xz[r][g] = bias[g] + sum_e emb[X[b][t]][e] * Wx[e][g]
// ---------------------------------------------------------------------------
__global__ void __launch_bounds__(256)
input_gemm_tc(const int*   __restrict__ X,
              const float* __restrict__ emb,
              const float* __restrict__ Wx,
              const float* __restrict__ bias) {
    unsigned* AhiW = (unsigned*)smem_raw;
    unsigned* AloW = AhiW + PLANE;
    unsigned* BhiW = AloW + PLANE;
    unsigned* BloW = BhiW + PLANE;
    __shared__ int xid[128];

    const int tid  = threadIdx.x;
    const int r0   = blockIdx.y * 128;
    const int g0   = blockIdx.x * 128;
    const int lane = tid & 31;
    const int wid  = tid >> 5;
    const int wr   = (wid & 3) * 32;
    const int wc   = (wid >> 2) * 64;
    const int g4r  = lane >> 2;
    const int lk   = lane & 3;
    const int lx2  = lk * 2;

    if (tid < 128) {
        int r = r0 + tid;
        xid[tid] = X[(r & 255) * T_ + (r >> 8)];
    }
    __syncthreads();

    {
        int row = tid >> 1;
        const float* src = emb + (size_t)xid[row] * E_;
        int qb = (tid & 1) * 8;
#pragma unroll
        for (int q = 0; q < 8; q++) {
            float4 v = *(const float4*)(src + (qb + q) * 4);
            uint2 hw, lw;
            split4(v, hw, lw);
            int widx = row * GW + (qb + q) * 2;
            *(uint2*)(AhiW + widx) = hw;
            *(uint2*)(AloW + widx) = lw;
        }
    }
    {
        int c = tid & 127, khalf = tid >> 7;
#pragma unroll
        for (int kk = 0; kk < 16; kk++) {
            int k0 = khalf * 32 + kk * 2;
            float a = Wx[(size_t)k0 * G4 + g0 + c];
            float b = Wx[(size_t)(k0 + 1) * G4 + g0 + c];
            __nv_bfloat16 ha, la, hb, lb;
            bf16_split(a, ha, la); bf16_split(b, hb, lb);
            int widx = c * GW + khalf * 16 + kk;
            BhiW[widx] = pack_bf2(ha, hb);
            BloW[widx] = pack_bf2(la, lb);
        }
    }
    __syncthreads();

    float acc[2][8][4];
#pragma unroll
    for (int f = 0; f < 2; f++)
#pragma unroll
        for (int s = 0; s < 8; s++)
#pragma unroll
            for (int i = 0; i < 4; i++) acc[f][s][i] = 0.f;

    gemm_chunk(AhiW, AloW, BhiW, BloW, wr, wc, g4r, lk, acc);

#pragma unroll
    for (int f = 0; f < 2; f++) {
        int rlo = r0 + wr + f * 16 + g4r;
#pragma unroll
        for (int sub = 0; sub < 8; sub++) {
            int g = g0 + wc + sub * 8 + lx2;
            float2 bb = *(const float2*)(bias + g);
            *(float2*)(g_xz + (size_t)rlo * G4 + g) =
                make_float2(acc[f][sub][0] + bb.x, acc[f][sub][1] + bb.y);
            *(float2*)(g_xz + (size_t)(rlo + 8) * G4 + g) =
                make_float2(acc[f][sub][2] + bb.x, acc[f][sub][3] + bb.y);
        }
    }
}

// ---------------------------------------------------------------------------
// Persistent LSTM recurrence (R6 structure) with:
//  - redundant per-chunk tail sync removed (double-buffer makes it safe)
//  - next-step xz prefetched before the grid barrier (latency hidden by poll)
//  - fast-division pointwise (sigf/tanhf_fast)
// ---------------------------------------------------------------------------
__global__ void __launch_bounds__(256, 1)
lstm_persistent(const float* __restrict__ Wh, const float* __restrict__ c0) {
    __nv_bfloat16* WhHi = (__nv_bfloat16*)(smem_raw + OFF_WHI);
    __nv_bfloat16* WhLo = (__nv_bfloat16*)(smem_raw + OFF_WLO);
    const unsigned* WhHiW = (const unsigned*)WhHi;
    const unsigned* WhLoW = (const unsigned*)WhLo;

    char* hBase = smem_raw + OFF_HA;   // buf0: hi,lo ; buf1: hi,lo

    const int tid  = threadIdx.x;
    const int bid  = blockIdx.x;
    const int cg   = bid & 31;          // n-group
    const int rg   = bid >> 5;          // row-group
    const int n0   = cg * 16;
    const int r0   = rg * 64;
    const int lane = tid & 31;
    const int wid  = tid >> 5;
    const int wr   = (wid & 3) * 16;    // warp row offset
    const int wc   = (wid >> 2) * 32;   // warp col offset
    const int g4r  = lane >> 2;
    const int lk   = lane & 3;
    const int lx2  = lk * 2;

    // ---- load + split Wh slice once: WhHi/WhLo[col][k], col = g*16+j ----
    for (int idx = tid; idx < 512 * 16; idx += 256) {
        int k = idx >> 4, q = idx & 15;
        int g = q >> 2, jj = (q & 3) * 4;
        float4 w = *(const float4*)(Wh + (size_t)k * G4 + g * N_ + n0 + jj);
        int cb = g * 16 + jj;
        __nv_bfloat16 hi, lo;
        bf16_split(w.x, hi, lo); WhHi[(cb + 0) * KS_BF + k] = hi; WhLo[(cb + 0) * KS_BF + k] = lo;
        bf16_split(w.y, hi, lo); WhHi[(cb + 1) * KS_BF + k] = hi; WhLo[(cb + 1) * KS_BF + k] = lo;
        bf16_split(w.z, hi, lo); WhHi[(cb + 2) * KS_BF + k] = hi; WhLo[(cb + 2) * KS_BF + k] = lo;
        bf16_split(w.w, hi, lo); WhHi[(cb + 3) * KS_BF + k] = hi; WhLo[(cb + 3) * KS_BF + k] = lo;
    }

    // ---- cell state in registers ----
    const int prow = tid >> 2;
    const int pj0  = (tid & 3) * 4;
    float4 creg = *(const float4*)(c0 + (size_t)(r0 + prow) * N_ + n0 + pj0);

    __syncthreads();

    const int srow0 = tid >> 4;            // staging rows tid>>4, +16, +32, +48
    const int skq   = tid & 15;            // k quad
    const int rlo   = r0 + wr + g4r;       // mma row base

    // ---- xz prefetch (t = 0) ----
    float2 xzp[8];
#pragma unroll
    for (int sub = 0; sub < 4; sub++) {
        int c    = wc + sub * 8 + lx2;
        int gate = c >> 4, jj = c & 15;
        size_t base = (size_t)gate * N_ + n0 + jj;
        xzp[sub * 2 + 0] = __ldcg((const float2*)(g_xz + base + (size_t)rlo * G4));
        xzp[sub * 2 + 1] = __ldcg((const float2*)(g_xz + base + (size_t)(rlo + 8) * G4));
    }

    for (int t = 0; t < T_; t++) {
        const float* __restrict__ h_in  = g_h[t & 1];
        float*       __restrict__ h_out = g_h[(t + 1) & 1];

        // ---- acc init from prefetched xz ----
        float acc[4][4];
#pragma unroll
        for (int sub = 0; sub < 4; sub++) {
            acc[sub][0] = xzp[sub * 2 + 0].x; acc[sub][1] = xzp[sub * 2 + 0].y;
            acc[sub][2] = xzp[sub * 2 + 1].x; acc[sub][3] = xzp[sub * 2 + 1].y;
        }

        // ---- GEMM over K=512 in 8 chunks of 64, double-buffered split-staging ----
        float4 pf[4];
#pragma unroll
        for (int q = 0; q < 4; q++) {
            pf[q] = __ldcg((const float4*)(h_in + (size_t)(r0 + srow0 + q * 16) * N_ + skq * 4));
        }

        for (int kc = 0; kc < 8; kc++) {
            unsigned* hHiW = (unsigned*)(hBase + (kc & 1) * 2 * HA_BYTES);
            unsigned* hLoW = hHiW + HA_BYTES / 4;

#pragma unroll
            for (int q = 0; q < 4; q++) {
                int row = srow0 + q * 16;
                uint2 hw, lw;
                split4(pf[q], hw, lw);
                int widx = row * HA_W + skq * 2;
                *(uint2*)(hHiW + widx) = hw;
                *(uint2*)(hLoW + widx) = lw;
            }
            if (kc < 7) {
#pragma unroll
                for (int q = 0; q < 4; q++) {
                    pf[q] = __ldcg((const float4*)(h_in + (size_t)(r0 + srow0 + q * 16) * N_ + (kc + 1) * 64 + skq * 4));
                }
            }
            __syncthreads();

            const int aBase = (wr + g4r) * HA_W + lk;
#pragma unroll
            for (int k16 = 0; k16 < 4; k16++) {
                const int aw = aBase + k16 * 8;
                unsigned aHi[4], aLo[4];
                aHi[0] = hHiW[aw];              aHi[1] = hHiW[aw + 8 * HA_W];
                aHi[2] = hHiW[aw + 4];          aHi[3] = hHiW[aw + 8 * HA_W + 4];
                aLo[0] = hLoW[aw];              aLo[1] = hLoW[aw + 8 * HA_W];
                aLo[2] = hLoW[aw + 4];          aLo[3] = hLoW[aw + 8 * HA_W + 4];
                const int kAbs = kc * 32 + lk + k16 * 8;
#pragma unroll
                for (int sub = 0; sub < 4; sub++) {
                    const int col = wc + sub * 8 + g4r;
                    const int bw  = col * KS_W + kAbs;
                    unsigned bHi[2], bLo[2];
                    bHi[0] = WhHiW[bw]; bHi[1] = WhHiW[bw + 4];
                    bLo[0] = WhLoW[bw]; bLo[1] = WhLoW[bw + 4];
                    mma_bf16(acc[sub], aHi, bHi);
                    mma_bf16(acc[sub], aHi, bLo);
                    mma_bf16(acc[sub], aLo, bHi);
                }
            }
            // no tail sync: next store targets the other buffer; sync at loop
            // head orders store(k+2) after all compute(k) via program order.
        }

        // ---- exchange z through SMEM (buf0 region; compute(7) used buf1) ----
        float* zs = (float*)hBase;
        {
            const int rl = wr + g4r;
#pragma unroll
            for (int sub = 0; sub < 4; sub++) {
                int c = wc + sub * 8 + lx2;
                *(float2*)(zs + (size_t)rl * Z_STRIDE + c)       = make_float2(acc[sub][0], acc[sub][1]);
                *(float2*)(zs + (size_t)(rl + 8) * Z_STRIDE + c) = make_float2(acc[sub][2], acc[sub][3]);
            }
        }
        __syncthreads();

        // ---- pointwise gates + c/h update (fast math) ----
        {
            const float* zr = zs + (size_t)prow * Z_STRIDE + pj0;
            float4 zi = *(const float4*)(zr + 0);
            float4 zf = *(const float4*)(zr + 16);
            float4 zg = *(const float4*)(zr + 32);
            float4 zo = *(const float4*)(zr + 48);

            float4 hv;
            creg.x = sigf(zf.x) * creg.x + sigf(zi.x) * tanhf_fast(zg.x); hv.x = sigf(zo.x) * tanhf_fast(creg.x);
            creg.y = sigf(zf.y) * creg.y + sigf(zi.y) * tanhf_fast(zg.y); hv.y = sigf(zo.y) * tanhf_fast(creg.y);
            creg.z = sigf(zf.z) * creg.z + sigf(zi.z) * tanhf_fast(zg.z); hv.z = sigf(zo.z) * tanhf_fast(creg.z);
            creg.w = sigf(zf.w) * creg.w + sigf(zi.w) * tanhf_fast(zg.w); hv.w = sigf(zo.w) * tanhf_fast(creg.w);

            size_t off = (size_t)(r0 + prow) * N_ + n0 + pj0;
            *(float4*)(h_out + off) = hv;
            *(float4*)(g_hs + (size_t)t * B_ * N_ + off) = hv;
        }

        // ---- prefetch next step's xz (latency hidden under barrier poll) ----
        if (t + 1 < T_) {
#pragma unroll
            for (int sub = 0; sub < 4; sub++) {
                int c    = wc + sub * 8 + lx2;
                int gate = c >> 4, jj = c & 15;
                size_t base = (size_t)(t + 1) * B_ * G4 + (size_t)gate * N_ + n0 + jj;
                xzp[sub * 2 + 0] = __ldcg((const float2*)(g_xz + base + (size_t)rlo * G4));
                xzp[sub * 2 + 1] = __ldcg((const float2*)(g_xz + base + (size_t)(rlo + 8) * G4));
            }
        }

        // ---- full-grid barrier (all 128 blocks resident) ----
        __threadfence();
        __syncthreads();
        if (tid == 0) {
            asm volatile("st.global.release.gpu.u32 [%0], %1;"
                         :: "l"(&g_flags[bid * 32]), "r"((unsigned)(t + 1)) : "memory");
        }
        if (tid < NBLK) {
            unsigned v;
            do {
                asm volatile("ld.global.acquire.gpu.u32 %0, [%1];"
                             : "=r"(v) : "l"(&g_flags[tid * 32]) : "memory");
                if (v >= (unsigned)(t + 1)) break;
                __nanosleep(20);
            } while (true);
        }
        __syncthreads();
    }
}

// ---------------------------------------------------------------------------
// Kernel D (tensor): logits[b][t][v] = bd[v] + sum_n hs[t][b][n] * Wd[n][v]
// ---------------------------------------------------------------------------
__global__ void __launch_bounds__(256)
out_gemm_tc(const float* __restrict__ Wd,
            const float* __restrict__ bd,
            float*       __restrict__ out) {
    unsigned* AhiW = (unsigned*)smem_raw;
    unsigned* AloW = AhiW + PLANE;
    unsigned* BhiW = AloW + PLANE;
    unsigned* BloW = BhiW + PLANE;

    const int tid  = threadIdx.x;
    const int r0   = blockIdx.x * 128;
    const int lane = tid & 31;
    const int wid  = tid >> 5;
    const int wr   = (wid & 3) * 32;
    const int wc   = (wid >> 2) * 64;
    const int g4r  = lane >> 2;
    const int lk   = lane & 3;
    const int lx2  = lk * 2;

    float acc[2][8][4];
#pragma unroll
    for (int f = 0; f < 2; f++)
#pragma unroll
        for (int s = 0; s < 8; s++)
#pragma unroll
            for (int i = 0; i < 4; i++) acc[f][s][i] = 0.f;

    const int srow = tid >> 1;
    const int sqb  = (tid & 1) * 8;
    const int bc   = tid & 127;
    const int bkh  = tid >> 7;

    for (int kc = 0; kc < 8; kc++) {
#pragma unroll
        for (int q = 0; q < 8; q++) {
            float4 v = __ldcg((const float4*)(g_hs + (size_t)(r0 + srow) * N_ + kc * 64 + (sqb + q) * 4));
            uint2 hw, lw;
            split4(v, hw, lw);
            int widx = srow * GW + (sqb + q) * 2;
            *(uint2*)(AhiW + widx) = hw;
            *(uint2*)(AloW + widx) = lw;
        }
#pragma unroll
        for (int kk = 0; kk < 16; kk++) {
            int k0 = kc * 64 + bkh * 32 + kk * 2;
            float a = Wd[(size_t)k0 * V_ + bc];
            float b = Wd[(size_t)(k0 + 1) * V_ + bc];
            __nv_bfloat16 ha, la, hb, lb;
            bf16_split(a, ha, la); bf16_split(b, hb, lb);
            int widx = bc * GW + bkh * 16 + kk;
            BhiW[widx] = pack_bf2(ha, hb);
            BloW[widx] = pack_bf2(la, lb);
        }
        __syncthreads();

        gemm_chunk(AhiW, AloW, BhiW, BloW, wr, wc, g4r, lk, acc);
        __syncthreads();
    }

#pragma unroll
    for (int f = 0; f < 2; f++) {
        int rlo = r0 + wr + f * 16 + g4r;
        int t0 = rlo >> 8,        b0 = rlo & 255;
        int t1 = (rlo + 8) >> 8,  b1 = (rlo + 8) & 255;
        size_t o0 = ((size_t)b0 * T_ + t0) * V_;
        size_t o1 = ((size_t)b1 * T_ + t1) * V_;
#pragma unroll
        for (int sub = 0; sub < 8; sub++) {
            int v = wc + sub * 8 + lx2;
            float2 bb = *(const float2*)(bd + v);
            *(float2*)(out + o0 + v) = make_float2(acc[f][sub][0] + bb.x, acc[f][sub][1] + bb.y);
            *(float2*)(out + o1 + v) = make_float2(acc[f][sub][2] + bb.x, acc[f][sub][3] + bb.y);
        }
    }
}

// ---------------------------------------------------------------------------
extern "C" void kernel_launch(void* const* d_in, const int* in_sizes, int n_in,
                              void* d_out, int out_size) {
    const int*   X    = (const int*)  d_in[0];
    const float* h0   = (const float*)d_in[1];
    const float* c0   = (const float*)d_in[2];
    const float* emb  = (const float*)d_in[3];
    const float* Wx   = (const float*)d_in[4];
    const float* Wh   = (const float*)d_in[5];
    const float* bias = (const float*)d_in[6];
    const float* Wd   = (const float*)d_in[7];
    const float* bd   = (const float*)d_in[8];
    float* out = (float*)d_out;

    cudaFuncSetAttribute(lstm_persistent, cudaFuncAttributeMaxDynamicSharedMemorySize, SMEM_TOTAL_LSTM);
    cudaFuncSetAttribute(input_gemm_tc,  cudaFuncAttributeMaxDynamicSharedMemorySize, SMEM_GEMM);
    cudaFuncSetAttribute(out_gemm_tc,    cudaFuncAttributeMaxDynamicSharedMemorySize, SMEM_GEMM);

    init_kernel<<<(B_ * N_ + 255) / 256, 256>>>(h0);
    input_gemm_tc<<<dim3(G4 / 128, (T_ * B_) / 128), 256, SMEM_GEMM>>>(X, emb, Wx, bias);
    lstm_persistent<<<NBLK, 256, SMEM_TOTAL_LSTM>>>(Wh, c0);
    out_gemm_tc<<<(T_ * B_) / 128, 256, SMEM_GEMM>>>(Wd, bd, out);
}